// round 1
// baseline (speedup 1.0000x reference)
#include <cuda_runtime.h>
#include <math.h>

#define Bn 8
#define Cch 32
#define Nn 512
#define Lt 64
#define BUF (Bn*Cch*Nn*Lt)

// Scratch (device globals — no allocation allowed)
__device__ float g_A[BUF];
__device__ float g_B[BUF];
__device__ float g_C[BUF];
__device__ float g_D[BUF];
__device__ float g_E[BUF];
__device__ float g_SK[BUF];
__device__ float g_A2[Nn*Nn];

// ---------------- start conv: x[8,2,512,64] -> h[8,32,512,64] ----------------
__global__ void k_start(const float* __restrict__ x, const float* __restrict__ W,
                        const float* __restrict__ bias, float* __restrict__ h) {
  int idx = blockIdx.x * 256 + threadIdx.x;
  if (idx >= BUF) return;
  int l = idx & 63;
  int n = (idx >> 6) & 511;
  int c = (idx >> 15) & 31;
  int b = idx >> 20;
  int xb = ((b * 2) * Nn + n) * Lt + l;
  h[idx] = x[xb] * W[c * 2] + x[xb + Nn * Lt] * W[c * 2 + 1] + bias[c];
}

// ---------------- A2 = adj @ adj  (512x512x512) ----------------
__global__ void k_a2(const float* __restrict__ adj, float* __restrict__ A2) {
  __shared__ float As[32][33], Bs[32][33];
  int tx = threadIdx.x, ty = threadIdx.y;  // (32, 8)
  int p0 = blockIdx.y * 32, m0 = blockIdx.x * 32;
  float acc[4] = {0.f, 0.f, 0.f, 0.f};
  for (int k0 = 0; k0 < Nn; k0 += 32) {
    #pragma unroll
    for (int r = 0; r < 4; r++) {
      As[ty + 8 * r][tx] = adj[(p0 + ty + 8 * r) * Nn + k0 + tx];
      Bs[ty + 8 * r][tx] = adj[(k0 + ty + 8 * r) * Nn + m0 + tx];
    }
    __syncthreads();
    #pragma unroll
    for (int k = 0; k < 32; k++) {
      float bv = Bs[k][tx];
      #pragma unroll
      for (int r = 0; r < 4; r++) acc[r] += As[ty + 8 * r][k] * bv;
    }
    __syncthreads();
  }
  #pragma unroll
  for (int r = 0; r < 4; r++) A2[(p0 + ty + 8 * r) * Nn + m0 + tx] = acc[r];
}

// ---------------- gated TCN + skip (modes: 0 init skip, 1 add skip, 2 final out) ----------------
__global__ void k_tcn(const float* __restrict__ h_in, float* __restrict__ t_out,
                      float* __restrict__ skipbuf, float* __restrict__ outp,
                      const float* __restrict__ Wf, const float* __restrict__ bfv,
                      const float* __restrict__ Wg, const float* __restrict__ bgv,
                      const float* __restrict__ Wsk, const float* __restrict__ bskv,
                      const float* __restrict__ obng, const float* __restrict__ obnb,
                      int Lin, int mode) {
  __shared__ float hs[32][73];
  __shared__ float hns[32][73];
  __shared__ float wfs[2048], wgs[2048], wsks[1024];
  int t = threadIdx.x;
  int n = blockIdx.x, b = blockIdx.y;
  int base = ((b * 32) * Nn + n) * Lt;

  for (int idx = t; idx < 32 * 64; idx += 256) {
    int c = idx >> 6, l = idx & 63;
    hs[c][l] = h_in[base + c * (Nn * Lt) + l];
  }
  for (int idx = t; idx < 2048; idx += 256) { wfs[idx] = Wf[idx]; wgs[idx] = Wg[idx]; }
  for (int idx = t; idx < 1024; idx += 256) wsks[idx] = Wsk[idx];
  __syncthreads();

  int o = t >> 3, sub = t & 7;
  int Lout = Lin - 1;
  int l0 = sub * 8;
  float f[8], g[8];
  float bfo = bfv[o], bgo = bgv[o];
  #pragma unroll
  for (int j = 0; j < 8; j++) { f[j] = bfo; g[j] = bgo; }

  for (int c = 0; c < 32; c++) {
    float wf0 = wfs[(o * 32 + c) * 2], wf1 = wfs[(o * 32 + c) * 2 + 1];
    float wg0 = wgs[(o * 32 + c) * 2], wg1 = wgs[(o * 32 + c) * 2 + 1];
    float hp = hs[c][l0];
    #pragma unroll
    for (int j = 0; j < 8; j++) {
      float hc = hs[c][l0 + j + 1];
      f[j] += hp * wf0 + hc * wf1;
      g[j] += hp * wg0 + hc * wg1;
      hp = hc;
    }
  }

  int obase = base + o * (Nn * Lt);
  #pragma unroll
  for (int j = 0; j < 8; j++) {
    int l = l0 + j;
    float hv = tanhf(f[j]) * (1.0f / (1.0f + expf(-g[j])));
    hns[o][l] = hv;
    if (mode != 2 && l < Lout) t_out[obase + l] = hv;
  }
  __syncthreads();

  float s[8];
  float bs = bskv[o];
  #pragma unroll
  for (int j = 0; j < 8; j++) s[j] = bs;
  for (int c = 0; c < 32; c++) {
    float w = wsks[o * 32 + c];
    #pragma unroll
    for (int j = 0; j < 8; j++) s[j] += w * hns[c][l0 + j];
  }

  if (mode == 0) {
    #pragma unroll
    for (int j = 0; j < 8; j++) {
      int l = l0 + j;
      if (l >= 2 && l < Lout) skipbuf[obase + l - 2] = s[j];
    }
  } else if (mode == 1) {
    #pragma unroll
    for (int j = 0; j < 8; j++) {
      int l = l0 + j;
      if (l >= 1 && l < Lout) skipbuf[obase + l - 1] += s[j];
    }
  } else {
    float inv = obng[o] * rsqrtf(1.0f + 1e-5f);
    float bb = obnb[o];
    #pragma unroll
    for (int j = 0; j < 8; j++) {
      int l = l0 + j;
      if (l < 61)
        outp[((b * 61 + l) * Nn + n) * 32 + o] = (skipbuf[obase + l] + s[j]) * inv + bb;
    }
  }
}

// ---------------- fused diffusion: X1 = adj^T . H, X2 = A2^T . H (per bc batch) ----------------
__global__ void k_diff(const float* __restrict__ H, const float* __restrict__ adj,
                       const float* __restrict__ A2,
                       float* __restrict__ X1, float* __restrict__ X2) {
  __shared__ float Hs[16][64], A1s[16][64], A2s[16][64];
  int t = threadIdx.x;
  int tx = t & 15, ty = t >> 4;
  int m0 = blockIdx.x * 64;
  int bc = blockIdx.y;
  int hbase = bc * (Nn * Lt);
  float acc1[4][4] = {}, acc2[4][4] = {};

  for (int k0 = 0; k0 < Nn; k0 += 16) {
    #pragma unroll
    for (int q = 0; q < 4; q++) {
      int idx = t + q * 256;
      int r = idx >> 6, cc = idx & 63;
      Hs[r][cc]  = H[hbase + (k0 + r) * Lt + cc];
      A1s[r][cc] = adj[(k0 + r) * Nn + m0 + cc];
      A2s[r][cc] = A2[(k0 + r) * Nn + m0 + cc];
    }
    __syncthreads();
    #pragma unroll
    for (int k = 0; k < 16; k++) {
      float hr[4], a1[4], a2[4];
      #pragma unroll
      for (int j = 0; j < 4; j++) hr[j] = Hs[k][tx + 16 * j];
      #pragma unroll
      for (int r = 0; r < 4; r++) { a1[r] = A1s[k][ty + 16 * r]; a2[r] = A2s[k][ty + 16 * r]; }
      #pragma unroll
      for (int r = 0; r < 4; r++)
        #pragma unroll
        for (int j = 0; j < 4; j++) {
          acc1[r][j] += a1[r] * hr[j];
          acc2[r][j] += a2[r] * hr[j];
        }
    }
    __syncthreads();
  }

  #pragma unroll
  for (int r = 0; r < 4; r++)
    #pragma unroll
    for (int j = 0; j < 4; j++) {
      int off = hbase + (m0 + ty + 16 * r) * Lt + tx + 16 * j;
      X1[off] = acc1[r][j];
      X2[off] = acc2[r][j];
    }
}

// ---------------- graph-conv 1x1 (96->32) + BN + residual + BN ----------------
__global__ void k_gcmix(const float* __restrict__ Ht, const float* __restrict__ X1,
                        const float* __restrict__ X2, const float* __restrict__ Res,
                        float* __restrict__ Out,
                        const float* __restrict__ Wgc, const float* __restrict__ bgc,
                        const float* __restrict__ gg, const float* __restrict__ gb,
                        const float* __restrict__ bng, const float* __restrict__ bnb,
                        int Lout) {
  __shared__ float hs[32][64], x1s[32][64], x2s[32][64];
  __shared__ float wgs[32 * 96];
  int t = threadIdx.x;
  int n = blockIdx.x, b = blockIdx.y;
  int base = ((b * 32) * Nn + n) * Lt;

  for (int idx = t; idx < 2048; idx += 256) {
    int c = idx >> 6, l = idx & 63;
    int gptr = base + c * (Nn * Lt) + l;
    hs[c][l] = Ht[gptr];
    x1s[c][l] = X1[gptr];
    x2s[c][l] = X2[gptr];
  }
  for (int idx = t; idx < 3072; idx += 256) wgs[idx] = Wgc[idx];
  __syncthreads();

  int og = t >> 5, lt = t & 31;
  float acc[4][2] = {};
  for (int c = 0; c < 32; c++) {
    float h0 = hs[c][lt],  h1 = hs[c][lt + 32];
    float p0 = x1s[c][lt], p1 = x1s[c][lt + 32];
    float q0 = x2s[c][lt], q1 = x2s[c][lt + 32];
    #pragma unroll
    for (int r = 0; r < 4; r++) {
      int o = og * 4 + r;
      float wh = wgs[o * 96 + c], w1 = wgs[o * 96 + 32 + c], w2 = wgs[o * 96 + 64 + c];
      acc[r][0] += wh * h0 + w1 * p0 + w2 * q0;
      acc[r][1] += wh * h1 + w1 * p1 + w2 * q1;
    }
  }

  const float inv0 = rsqrtf(1.0f + 1e-5f);
  #pragma unroll
  for (int r = 0; r < 4; r++) {
    int o = og * 4 + r;
    float gi = gg[o] * inv0, gbb = gb[o];
    float bi = bng[o] * inv0, bbb = bnb[o];
    int ob = base + o * (Nn * Lt);
    #pragma unroll
    for (int jj = 0; jj < 2; jj++) {
      int l = lt + 32 * jj;
      if (l < Lout) {
        float v = (acc[r][jj] + bgc[o]) * gi + gbb;
        v += Res[ob + l + 1];
        Out[ob + l] = v * bi + bbb;
      }
    }
  }
}

extern "C" void kernel_launch(void* const* d_in, const int* in_sizes, int n_in,
                              void* d_out, int out_size) {
  const float* x      = (const float*)d_in[0];
  const float* adj    = (const float*)d_in[1];
  const float* Wstart = (const float*)d_in[2];
  const float* bstart = (const float*)d_in[3];
  const float* Wf     = (const float*)d_in[4];
  const float* bf     = (const float*)d_in[5];
  const float* Wg     = (const float*)d_in[6];
  const float* bg     = (const float*)d_in[7];
  const float* Wsk    = (const float*)d_in[8];
  const float* bsk    = (const float*)d_in[9];
  const float* Wgc    = (const float*)d_in[10];
  const float* bgc    = (const float*)d_in[11];
  const float* gcg    = (const float*)d_in[12];
  const float* gcb    = (const float*)d_in[13];
  const float* bng    = (const float*)d_in[14];
  const float* bnb    = (const float*)d_in[15];
  const float* obng   = (const float*)d_in[16];
  const float* obnb   = (const float*)d_in[17];
  float* out = (float*)d_out;

  float *A, *Bu, *Cu, *Du, *Eu, *SK, *A2p;
  cudaGetSymbolAddress((void**)&A,   g_A);
  cudaGetSymbolAddress((void**)&Bu,  g_B);
  cudaGetSymbolAddress((void**)&Cu,  g_C);
  cudaGetSymbolAddress((void**)&Du,  g_D);
  cudaGetSymbolAddress((void**)&Eu,  g_E);
  cudaGetSymbolAddress((void**)&SK,  g_SK);
  cudaGetSymbolAddress((void**)&A2p, g_A2);

  dim3 bn_grid(Nn, Bn);          // (512, 8)
  dim3 diff_grid(8, Bn * Cch);   // (8 m-tiles, 256 batches)

  k_start<<<(BUF + 255) / 256, 256>>>(x, Wstart, bstart, A);
  k_a2<<<dim3(16, 16), dim3(32, 8)>>>(adj, A2p);

  // ---- layer 0 (Lin=64 -> Lout=63) ----
  k_tcn<<<bn_grid, 256>>>(A, Bu, SK, nullptr,
                          Wf, bf, Wg, bg, Wsk, bsk, nullptr, nullptr, 64, 0);
  k_diff<<<diff_grid, 256>>>(Bu, adj, A2p, Cu, Du);
  k_gcmix<<<bn_grid, 256>>>(Bu, Cu, Du, A, Eu,
                            Wgc, bgc, gcg, gcb, bng, bnb, 63);

  // ---- layer 1 (Lin=63 -> Lout=62) ----
  k_tcn<<<bn_grid, 256>>>(Eu, Bu, SK, nullptr,
                          Wf + 2048, bf + 32, Wg + 2048, bg + 32,
                          Wsk + 1024, bsk + 32, nullptr, nullptr, 63, 1);
  k_diff<<<diff_grid, 256>>>(Bu, adj, A2p, Cu, Du);
  k_gcmix<<<bn_grid, 256>>>(Bu, Cu, Du, Eu, A,
                            Wgc + 3072, bgc + 32, gcg + 32, gcb + 32,
                            bng + 32, bnb + 32, 62);

  // ---- layer 2 (Lin=62 -> Lout=61, fused final BN + transpose) ----
  k_tcn<<<bn_grid, 256>>>(A, Bu, SK, out,
                          Wf + 4096, bf + 64, Wg + 4096, bg + 64,
                          Wsk + 2048, bsk + 64, obng, obnb, 62, 2);
}